// round 11
// baseline (speedup 1.0000x reference)
#include <cuda_runtime.h>
#include <cuda_bf16.h>
#include <math.h>

#define NB 64
#define NT 512
#define NM 8
#define NV 50
#define TT  128          // timesteps per CTA tile
#define NTILE 4          // NT / TT
#define TPB 128
#define WPAD 56          // padded w (7 n-tiles of 8)
#define GP 51            // gbuf row pad (floats); stores GUARDED to wc<NV
#define LUTN 1024
#define LUTF 1024.0f

typedef unsigned int u32;

__device__ float2 g_lut[NM][LUTN];

// ---------------- helpers ----------------
__device__ __forceinline__ u32 smem_u32(const void* p){
  u32 a; asm("{ .reg .u64 t; cvta.to.shared.u64 t, %1; cvt.u32.u64 %0, t; }" : "=r"(a) : "l"(p));
  return a;
}
__device__ __forceinline__ float ex2f(float x){ float r; asm("ex2.approx.f32 %0, %1;" : "=f"(r) : "f"(x)); return r; }
__device__ __forceinline__ float rcpf(float x){ float r; asm("rcp.approx.f32 %0, %1;" : "=f"(r) : "f"(x)); return r; }

__device__ __forceinline__ void mma_bf16(float* d, const u32* a, u32 b0, u32 b1){
  asm volatile("mma.sync.aligned.m16n8k16.row.col.f32.bf16.bf16.f32 "
    "{%0,%1,%2,%3}, {%4,%5,%6,%7}, {%8,%9}, {%0,%1,%2,%3};"
    : "+f"(d[0]), "+f"(d[1]), "+f"(d[2]), "+f"(d[3])
    : "r"(a[0]), "r"(a[1]), "r"(a[2]), "r"(a[3]), "r"(b0), "r"(b1));
}
// Non-transposed ldmatrix: smem rows = n, row elements = k (consecutive k packed) -> .col B frag.
__device__ __forceinline__ void ldsm2(u32 &r0, u32 &r1, u32 addr){
  asm volatile("ldmatrix.sync.aligned.m8n8.x2.shared.b16 {%0,%1}, [%2];"
    : "=r"(r0), "=r"(r1) : "r"(addr));
}

// split a pair of fp32 into packed bf16 hi and bf16 lo-residual (elem0 in low half)
__device__ __forceinline__ void split2(float f0, float f1, u32 &hp, u32 &lp){
  __nv_bfloat16 h0 = __float2bfloat16(f0), h1 = __float2bfloat16(f1);
  float l0 = f0 - __bfloat162float(h0);
  float l1 = f1 - __bfloat162float(h1);
  __nv_bfloat16 g0 = __float2bfloat16(l0), g1 = __float2bfloat16(l1);
  hp = ((u32)__bfloat16_as_ushort(h1) << 16) | (u32)__bfloat16_as_ushort(h0);
  lp = ((u32)__bfloat16_as_ushort(g1) << 16) | (u32)__bfloat16_as_ushort(g0);
}

// ---------------- LUT builder ----------------
__global__ void lut_build(const float* __restrict__ w1, const float* __restrict__ b1,
                          const float* __restrict__ w2, const float* __restrict__ b2)
{
  const int m = blockIdx.x;
  const float LOG2E = 1.4426950408889634f;
  float W1[8], B1[8], W2[8];
  float bias = b2[m];
  float M = bias, lim = bias;
  #pragma unroll
  for (int j = 0; j < 8; j++){
    W1[j] = w1[m*8+j]; B1[j] = b1[m*8+j]; W2[j] = w2[m*8+j];
    M += fabsf(W2[j]);
    lim += W2[j] * (W1[j] > 0.f ? 1.f : (W1[j] < 0.f ? -1.f : tanhf(B1[j])));
  }
  M *= LOG2E; lim *= LOG2E;

  for (int i = threadIdx.x; i < LUTN; i += blockDim.x){
    float f0, f1;
    {
      float u = (float)i / LUTF;
      float h = u / (1.f - u);
      float s = bias;
      #pragma unroll
      for (int j = 0; j < 8; j++) s += W2[j] * tanhf(fmaf(h, W1[j], B1[j]));
      f0 = s * LOG2E;
    }
    if (i + 1 == LUTN) f1 = lim;
    else {
      float u = (float)(i + 1) / LUTF;
      float h = u / (1.f - u);
      float s = bias;
      #pragma unroll
      for (int j = 0; j < 8; j++) s += W2[j] * tanhf(fmaf(h, W1[j], B1[j]));
      f1 = s * LOG2E;
    }
    g_lut[m][i] = make_float2(f0 - M, f1 - f0);
  }
}

// ---------------- main kernel ----------------
__device__ __forceinline__ void node_update(float gval, float A, float C,
                                            const float2* __restrict__ sLUT,
                                            float &l, float &acc)
{
  float h = fmaxf(fmaf(gval, A, C), 0.f);
  float r = rcpf(1.f + h);
  float q = fmaf(r, -LUTF, LUTF);
  int   i = (int)q;
  i = min(max(i, 0), LUTN - 1);
  float fr = q - (float)i;
  float2 e = sLUT[i];
  float p = ex2f(fmaf(fr, e.y, e.x));
  l += p;
  acc = fmaf(h, p, acc);
}

__global__ void __launch_bounds__(TPB)
ima_kernel(const float* __restrict__ x,  const float* __restrict__ PA,
           const float* __restrict__ conv_w, const float* __restrict__ conv_b,
           const float* __restrict__ bn_gamma, const float* __restrict__ bn_beta,
           const float* __restrict__ bn_mean,  const float* __restrict__ bn_var,
           float* __restrict__ out)
{
  // B = PA^T: smem rows = w (n dim), 64 v (k dim) bf16 = 128 B/row, XOR-swizzled 16B chunks
  __shared__ __align__(128) unsigned char p_hi[WPAD * 128];   // 7 KB
  __shared__ __align__(128) unsigned char p_lo[WPAD * 128];   // 7 KB
  __shared__ float  gbuf[TT * GP];                            // 25.5 KB
  __shared__ float2 sLUT[LUTN];                               // 8 KB  (total 48640 B)

  const int tid  = threadIdx.x;
  const int wid  = tid >> 5;
  const int lane = tid & 31;
  const int gid  = lane >> 2;       // groupID 0..7
  const int tig  = lane & 3;        // threadID_in_group 0..3

  const int blk  = blockIdx.x;      // 0..2047
  const int tile = blk & (NTILE - 1);
  const int bm   = blk / NTILE;
  const int m    = bm & (NM - 1);
  const int b    = bm / NM;

  // ---- zero B tiles (backdrop for v>=50 / w>=50) ----
  for (int i = tid; i < (WPAD * 128) / 4; i += TPB){
    ((u32*)p_hi)[i] = 0u;
    ((u32*)p_lo)[i] = 0u;
  }
  for (int i = tid; i < LUTN; i += TPB) sLUT[i] = g_lut[m][i];

  // ---- A fragments straight from gmem ----
  const float* xg = x + ((size_t)(b * NM + m) * NV) * NT + tile * TT;
  const int trow = wid * 32 + gid;

  u32 Ah[2][4][4], Al[2][4][4];
  #pragma unroll
  for (int mt = 0; mt < 2; mt++){
    #pragma unroll
    for (int kt = 0; kt < 4; kt++){
      int r0 = trow + mt * 16;
      int r1 = r0 + 8;
      int v0 = kt * 16 + 2 * tig;
      int v8 = v0 + 8;
      float x00 = (v0     < NV) ? xg[(size_t)(v0    ) * NT + r0] : 0.f;
      float x01 = (v0 + 1 < NV) ? xg[(size_t)(v0 + 1) * NT + r0] : 0.f;
      float x10 = (v0     < NV) ? xg[(size_t)(v0    ) * NT + r1] : 0.f;
      float x11 = (v0 + 1 < NV) ? xg[(size_t)(v0 + 1) * NT + r1] : 0.f;
      float y00 = (v8     < NV) ? xg[(size_t)(v8    ) * NT + r0] : 0.f;
      float y01 = (v8 + 1 < NV) ? xg[(size_t)(v8 + 1) * NT + r0] : 0.f;
      float y10 = (v8     < NV) ? xg[(size_t)(v8    ) * NT + r1] : 0.f;
      float y11 = (v8 + 1 < NV) ? xg[(size_t)(v8 + 1) * NT + r1] : 0.f;
      split2(x00, x01, Ah[mt][kt][0], Al[mt][kt][0]);
      split2(x10, x11, Ah[mt][kt][1], Al[mt][kt][1]);
      split2(y00, y01, Ah[mt][kt][2], Al[mt][kt][2]);
      split2(y10, y11, Ah[mt][kt][3], Al[mt][kt][3]);
    }
  }

  __syncthreads();   // zeros visible before scatter

  // ---- stage P^T swizzled (coalesced gmem reads over w) ----
  const float* PAm = PA + m * NV * NV;
  for (int i = tid; i < NV * NV; i += TPB){
    int v = i / NV;
    int w = i - v * NV;           // consecutive across threads
    float p = PAm[i];             // PA[m][v][w]
    __nv_bfloat16 h = __float2bfloat16(p);
    float lo = p - __bfloat162float(h);
    __nv_bfloat16 hl = __float2bfloat16(lo);
    u32 off = (u32)w * 128u + (u32)(((v >> 3) ^ (w & 7)) * 16) + (u32)((v & 7) * 2);
    *(unsigned short*)(p_hi + off) = __bfloat16_as_ushort(h);
    *(unsigned short*)(p_lo + off) = __bfloat16_as_ushort(hl);
  }
  __syncthreads();

  // ---- MMA main: D = Ah*Bh + Ah*Bl + Al*Bh ----
  const u32 phib = smem_u32(p_hi);
  const u32 plob = smem_u32(p_lo);
  const int lm    = lane & 15;
  const int wrow8 = lm & 7;
  const int msel  = (lm >> 3) & 1;

  #pragma unroll
  for (int nt = 0; nt < 7; nt++){
    float d0[4] = {0.f, 0.f, 0.f, 0.f};
    float d1[4] = {0.f, 0.f, 0.f, 0.f};
    #pragma unroll
    for (int kt = 0; kt < 4; kt++){
      int wrow  = nt * 8 + wrow8;
      int chunk = 2 * kt + msel;
      u32 boff  = (u32)wrow * 128u + (u32)((chunk ^ (wrow & 7)) * 16);
      u32 bh0, bh1, bl0, bl1;
      ldsm2(bh0, bh1, phib + boff);
      ldsm2(bl0, bl1, plob + boff);
      mma_bf16(d0, Ah[0][kt], bh0, bh1);
      mma_bf16(d1, Ah[1][kt], bh0, bh1);
      mma_bf16(d0, Ah[0][kt], bl0, bl1);
      mma_bf16(d1, Ah[1][kt], bl0, bl1);
      mma_bf16(d0, Al[0][kt], bh0, bh1);
      mma_bf16(d1, Al[1][kt], bh0, bh1);
    }
    // D frag -> gbuf. GUARDED: only real columns (wc < NV) are stored.
    // (THE R8-R10 BUG: unguarded 56-col writes into a 51-col-pitch buffer
    //  corrupted the next row's cols 0..4 and stomped sLUT.)
    int wc = nt * 8 + 2 * tig;
    if (wc < NV){
      gbuf[(trow     ) * GP + wc] = d0[0];
      gbuf[(trow +  8) * GP + wc] = d0[2];
      gbuf[(trow + 16) * GP + wc] = d1[0];
      gbuf[(trow + 24) * GP + wc] = d1[2];
    }
    if (wc + 1 < NV){
      gbuf[(trow     ) * GP + wc + 1] = d0[1];
      gbuf[(trow +  8) * GP + wc + 1] = d0[3];
      gbuf[(trow + 16) * GP + wc + 1] = d1[1];
      gbuf[(trow + 24) * GP + wc + 1] = d1[3];
    }
  }

  __syncthreads();

  // ---- epilogue: one timestep per thread ----
  const float scale = bn_gamma[m] * rsqrtf(bn_var[m] + 1e-5f);
  const float A = conv_w[m] * scale;
  const float C = (conv_b[m] - bn_mean[m]) * scale + bn_beta[m];

  float l = 0.f, acc = 0.f;
  const float* grow = &gbuf[tid * GP];
  #pragma unroll
  for (int c = 0; c < NV; c++)
    node_update(grow[c], A, C, sLUT, l, acc);

  out[(size_t)(b * NM + m) * NT + tile * TT + tid] = acc / l;
}

extern "C" void kernel_launch(void* const* d_in, const int* in_sizes, int n_in,
                              void* d_out, int out_size)
{
  (void)in_sizes; (void)n_in; (void)out_size;
  lut_build<<<NM, 256>>>((const float*)d_in[8],  (const float*)d_in[9],
                         (const float*)d_in[10], (const float*)d_in[11]);
  ima_kernel<<<NB * NM * NTILE, TPB>>>(
      (const float*)d_in[0],  (const float*)d_in[1],
      (const float*)d_in[2],  (const float*)d_in[3],
      (const float*)d_in[4],  (const float*)d_in[5],
      (const float*)d_in[6],  (const float*)d_in[7],
      (float*)d_out);
}